// round 1
// baseline (speedup 1.0000x reference)
#include <cuda_runtime.h>
#include <cuda_bf16.h>

// Problem constants (fixed-shape benchmark)
#define Bq   4
#define Tq   1024
#define Cq   1024
#define Hq   16
#define HKVq 4
#define Dq   64
#define REPq 4
#define GATE_CH 12
#define MROWS (Bq*Tq)        // 4096
#define NQKV  (Hq*Dq + 2*HKVq*Dq)  // 1536

// Scratch (device globals — no allocation allowed)
__device__ float g_raw[MROWS * NQKV];       // QKV raw projections
__device__ float g_Q[Bq*Hq*Tq*Dq];          // [b,h,t,d]
__device__ float g_K[Bq*HKVq*Tq*Dq];        // [b,g,t,d]
__device__ float g_V[Bq*HKVq*Tq*Dq];        // [b,g,t,d]
__device__ float g_Y[MROWS * Cq];           // attention output [b*t, h*d]

__device__ __forceinline__ float warpSum(float v) {
    #pragma unroll
    for (int o = 16; o; o >>= 1) v += __shfl_xor_sync(0xFFFFFFFFu, v, o);
    return v;
}
__device__ __forceinline__ float warpMax(float v) {
    #pragma unroll
    for (int o = 16; o; o >>= 1) v = fmaxf(v, __shfl_xor_sync(0xFFFFFFFFu, v, o));
    return v;
}

// ---------------------------------------------------------------------------
// C[M,N] = A[M,K] @ B[N,K]^T   (A,B row-major; C row-major with leading dim ldc)
// BM=BN=64, BK=16, 256 threads, 4x4 per-thread microtile.
// Requires M%64==0, N%64==0, K%16==0 (true for all uses here).
// ---------------------------------------------------------------------------
__global__ void gemm_nt(const float* __restrict__ A, const float* __restrict__ B,
                        float* __restrict__ C, int K, int ldc) {
    __shared__ __align__(16) float As[16][64];
    __shared__ __align__(16) float Bs[16][64];
    const int tid = threadIdx.x;
    const int m0 = blockIdx.y * 64;
    const int n0 = blockIdx.x * 64;
    const int ty = tid >> 4;       // 0..15
    const int tx = tid & 15;       // 0..15
    const int lrow = tid >> 2;     // 0..63
    const int lc4  = (tid & 3) * 4;

    float acc[4][4];
    #pragma unroll
    for (int i = 0; i < 4; i++)
        #pragma unroll
        for (int j = 0; j < 4; j++) acc[i][j] = 0.f;

    const float* Arow = A + (long)(m0 + lrow) * K;
    const float* Brow = B + (long)(n0 + lrow) * K;

    for (int k0 = 0; k0 < K; k0 += 16) {
        float4 a = *(const float4*)(Arow + k0 + lc4);
        float4 b = *(const float4*)(Brow + k0 + lc4);
        As[lc4 + 0][lrow] = a.x; As[lc4 + 1][lrow] = a.y;
        As[lc4 + 2][lrow] = a.z; As[lc4 + 3][lrow] = a.w;
        Bs[lc4 + 0][lrow] = b.x; Bs[lc4 + 1][lrow] = b.y;
        Bs[lc4 + 2][lrow] = b.z; Bs[lc4 + 3][lrow] = b.w;
        __syncthreads();
        #pragma unroll
        for (int kk = 0; kk < 16; kk++) {
            float ar[4], br[4];
            #pragma unroll
            for (int i = 0; i < 4; i++) ar[i] = As[kk][ty * 4 + i];
            #pragma unroll
            for (int j = 0; j < 4; j++) br[j] = Bs[kk][tx * 4 + j];
            #pragma unroll
            for (int i = 0; i < 4; i++)
                #pragma unroll
                for (int j = 0; j < 4; j++) acc[i][j] += ar[i] * br[j];
        }
        __syncthreads();
    }
    #pragma unroll
    for (int i = 0; i < 4; i++) {
        float* crow = C + (long)(m0 + ty * 4 + i) * ldc + n0 + tx * 4;
        #pragma unroll
        for (int j = 0; j < 4; j++) crow[j] = acc[i][j];
    }
}

// ---------------------------------------------------------------------------
// Prep: gate + ve add, RoPE, RMS-norm, rearrange.
// One block per (b,t) row; 128 threads (4 warps). Warp w handles
// q heads {w, w+4, w+8, w+12}, kv head w.
// ---------------------------------------------------------------------------
__global__ void prep_kernel(const float* __restrict__ raw,
                            const float* __restrict__ x,
                            const float* __restrict__ ve,
                            const float* __restrict__ cosv,
                            const float* __restrict__ sinv,
                            const float* __restrict__ Wg,
                            float* __restrict__ Q,
                            float* __restrict__ Kd,
                            float* __restrict__ Vd) {
    const int r = blockIdx.x;             // b*T + t
    const int b = r >> 10;
    const int t = r & 1023;
    const int w = threadIdx.x >> 5;
    const int lane = threadIdx.x & 31;

    const float c = cosv[t * 32 + lane];
    const float s = sinv[t * 32 + lane];
    const float* row = raw + (long)r * NQKV;
    const float EPS = 1.1920928955078125e-07f;

    // q heads
    #pragma unroll
    for (int hh = 0; hh < 4; hh++) {
        int h = w + hh * 4;
        float x1 = row[h * 64 + lane];
        float x2 = row[h * 64 + 32 + lane];
        float y1 = x1 * c + x2 * s;
        float y2 = -x1 * s + x2 * c;
        float ss = warpSum(y1 * y1 + y2 * y2);
        float rn = rsqrtf(ss * (1.f / 64.f) + EPS) * 1.2f;
        float* qo = Q + ((long)(b * Hq + h) * Tq + t) * 64;
        qo[lane] = y1 * rn;
        qo[lane + 32] = y2 * rn;
    }
    // k head w
    {
        float x1 = row[1024 + w * 64 + lane];
        float x2 = row[1024 + w * 64 + 32 + lane];
        float y1 = x1 * c + x2 * s;
        float y2 = -x1 * s + x2 * c;
        float ss = warpSum(y1 * y1 + y2 * y2);
        float rn = rsqrtf(ss * (1.f / 64.f) + EPS) * 1.2f;
        float* ko = Kd + ((long)(b * HKVq + w) * Tq + t) * 64;
        ko[lane] = y1 * rn;
        ko[lane + 32] = y2 * rn;
    }
    // gate + v head w
    {
        float gv = 0.f;
        if (lane < GATE_CH) gv = x[(long)r * Cq + lane] * Wg[w * GATE_CH + lane];
        gv = warpSum(gv);
        float gate = 3.f / (1.f + __expf(-gv));
        float v1 = row[1280 + w * 64 + lane]      + gate * ve[(long)r * 256 + w * 64 + lane];
        float v2 = row[1280 + w * 64 + 32 + lane] + gate * ve[(long)r * 256 + w * 64 + 32 + lane];
        float* vo = Vd + ((long)(b * HKVq + w) * Tq + t) * 64;
        vo[lane] = v1;
        vo[lane + 32] = v2;
    }
}

// ---------------------------------------------------------------------------
// Sliding-window attention.
// Grid: (T/64, B*H). Block: 256 threads (8 warps, 8 queries each).
// K/V tile of 320 keys in smem (pitch 65 -> conflict-free lane-over-key dots).
// ---------------------------------------------------------------------------
#define QTILE 64
#define KTILE 320
#define KPITCH 65
#define ATTN_SMEM ((2 * KTILE * KPITCH + 8 * KTILE + 8 * 64) * 4)

__global__ void attn_kernel(const float* __restrict__ Q,
                            const float* __restrict__ Kd,
                            const float* __restrict__ Vd,
                            float* __restrict__ Y,
                            const int* __restrict__ wptr) {
    extern __shared__ float sm[];
    float* Ks  = sm;
    float* Vs  = Ks + KTILE * KPITCH;
    float* psm = Vs + KTILE * KPITCH;
    float* qsm = psm + 8 * KTILE;

    const int W = *wptr;
    const int bh = blockIdx.y;            // b*H + h
    const int b = bh >> 4;
    const int h = bh & 15;
    const int g = h >> 2;                 // rep = 4
    const int qt0 = blockIdx.x * QTILE;
    const int ks0 = qt0 - 256;

    const float* Kbase = Kd + (long)(b * HKVq + g) * Tq * 64;
    const float* Vbase = Vd + (long)(b * HKVq + g) * Tq * 64;
    const float* Qbase = Q + (long)bh * Tq * 64;

    for (int idx = threadIdx.x; idx < KTILE * 64; idx += blockDim.x) {
        int jl = idx >> 6, d = idx & 63;
        int jg = ks0 + jl;
        if (jg >= 0) {
            Ks[jl * KPITCH + d] = Kbase[jg * 64 + d];
            Vs[jl * KPITCH + d] = Vbase[jg * 64 + d];
        }
    }
    __syncthreads();

    const int w = threadIdx.x >> 5;
    const int lane = threadIdx.x & 31;
    float* pw = psm + w * KTILE;
    float* qw = qsm + w * 64;

    for (int qq = 0; qq < 8; qq++) {
        const int i = qt0 + w * 8 + qq;
        qw[lane]      = Qbase[i * 64 + lane];
        qw[lane + 32] = Qbase[i * 64 + 32 + lane];
        __syncwarp();

        const int lo = max(0, i - W);
        const int n = i - lo + 1;

        float m = -1e30f;
        for (int jj = lane; jj < n; jj += 32) {
            const float* kr = Ks + (lo + jj - ks0) * KPITCH;
            float sc = 0.f;
            #pragma unroll
            for (int d = 0; d < 64; d++) sc += qw[d] * kr[d];
            sc *= 0.125f;
            pw[jj] = sc;
            m = fmaxf(m, sc);
        }
        m = warpMax(m);

        float sum = 0.f;
        for (int jj = lane; jj < n; jj += 32) {
            float p = __expf(pw[jj] - m);
            pw[jj] = p;
            sum += p;
        }
        sum = warpSum(sum);
        __syncwarp();
        const float inv = 1.f / sum;

        float a0 = 0.f, a1 = 0.f;
        for (int jj = 0; jj < n; jj++) {
            float p = pw[jj];
            const float* vr = Vs + (lo + jj - ks0) * KPITCH;
            a0 += p * vr[lane];
            a1 += p * vr[lane + 32];
        }
        float* yo = Y + ((long)(b * Tq + i) * Cq) + h * 64;
        yo[lane]      = a0 * inv;
        yo[lane + 32] = a1 * inv;
        __syncwarp();
    }
}

// ---------------------------------------------------------------------------
extern "C" void kernel_launch(void* const* d_in, const int* in_sizes, int n_in,
                              void* d_out, int out_size) {
    const float* x    = (const float*)d_in[0];
    const float* ve   = (const float*)d_in[1];
    const float* cosv = (const float*)d_in[2];
    const float* sinv = (const float*)d_in[3];
    const float* Wq   = (const float*)d_in[4];
    const float* Wk   = (const float*)d_in[5];
    const float* Wv   = (const float*)d_in[6];
    const float* Wo   = (const float*)d_in[7];
    const float* Wg   = (const float*)d_in[8];
    const int*   wptr = (const int*)d_in[9];
    float* out = (float*)d_out;

    float *raw, *Q, *K, *V, *Y;
    cudaGetSymbolAddress((void**)&raw, g_raw);
    cudaGetSymbolAddress((void**)&Q, g_Q);
    cudaGetSymbolAddress((void**)&K, g_K);
    cudaGetSymbolAddress((void**)&V, g_V);
    cudaGetSymbolAddress((void**)&Y, g_Y);

    cudaFuncSetAttribute(attn_kernel,
                         cudaFuncAttributeMaxDynamicSharedMemorySize, ATTN_SMEM);

    // QKV projections into raw [4096, 1536]
    gemm_nt<<<dim3(Hq*Dq/64, MROWS/64), 256>>>(x, Wq, raw,        Cq, NQKV);
    gemm_nt<<<dim3(HKVq*Dq/64, MROWS/64), 256>>>(x, Wk, raw+1024, Cq, NQKV);
    gemm_nt<<<dim3(HKVq*Dq/64, MROWS/64), 256>>>(x, Wv, raw+1280, Cq, NQKV);

    // gate/ve/rope/rmsnorm/rearrange
    prep_kernel<<<MROWS, 128>>>(raw, x, ve, cosv, sinv, Wg, Q, K, V);

    // sliding-window attention
    attn_kernel<<<dim3(Tq/QTILE, Bq*Hq), 256, ATTN_SMEM>>>(Q, K, V, Y, wptr);

    // output projection
    gemm_nt<<<dim3(Cq/64, MROWS/64), 256>>>(Y, Wo, out, Cq, Cq);
    (void)in_sizes; (void)n_in; (void)out_size;
}

// round 2
// speedup vs baseline: 1.7442x; 1.7442x over previous
#include <cuda_runtime.h>
#include <cuda_bf16.h>

// Problem constants (fixed-shape benchmark)
#define Bq   4
#define Tq   1024
#define Cq   1024
#define Hq   16
#define HKVq 4
#define Dq   64
#define GATE_CH 12
#define MROWS (Bq*Tq)              // 4096
#define NQKV  (Hq*Dq + 2*HKVq*Dq) // 1536

// Scratch (device globals — no allocation allowed)
__device__ float g_raw[MROWS * NQKV];
__device__ float g_Q[Bq*Hq*Tq*Dq];
__device__ float g_K[Bq*HKVq*Tq*Dq];
__device__ float g_V[Bq*HKVq*Tq*Dq];
__device__ float g_Y[MROWS * Cq];

__device__ __forceinline__ float warpSum(float v) {
    #pragma unroll
    for (int o = 16; o; o >>= 1) v += __shfl_xor_sync(0xFFFFFFFFu, v, o);
    return v;
}
__device__ __forceinline__ float warpMax(float v) {
    #pragma unroll
    for (int o = 16; o; o >>= 1) v = fmaxf(v, __shfl_xor_sync(0xFFFFFFFFu, v, o));
    return v;
}
__device__ __forceinline__ unsigned f2tf32(float x) {
    unsigned r;
    asm("cvt.rna.tf32.f32 %0, %1;" : "=r"(r) : "f"(x));
    return r;
}

// ---------------------------------------------------------------------------
// TF32 tensor-core GEMM: C[M,N] = A[M,K] @ B[N,K]^T
// CTA tile 128x128, BK=32, 256 threads (8 warps), warp tile 32x64.
// smem layout [row][k] pitch 36: conflict-free 128b stores AND fragment loads.
// Requires M%128==0, N%128==0, K%32==0.
// ---------------------------------------------------------------------------
#define BM 128
#define BN 128
#define BK 32
#define PIT 36

__global__ __launch_bounds__(256) void gemm_tf32(
        const float* __restrict__ A, const float* __restrict__ B,
        float* __restrict__ C, int K, int ldc) {
    __shared__ __align__(16) unsigned As[BM * PIT];
    __shared__ __align__(16) unsigned Bs[BN * PIT];

    const int tid = threadIdx.x;
    const int m0 = blockIdx.y * BM;
    const int n0 = blockIdx.x * BN;
    const int wid = tid >> 5, lane = tid & 31;
    const int wm = (wid & 3) * 32;     // warp m-offset within CTA
    const int wn = (wid >> 2) * 64;    // warp n-offset within CTA
    const int g = lane >> 2, c = lane & 3;

    float acc[2][8][4];
    #pragma unroll
    for (int mi = 0; mi < 2; mi++)
        #pragma unroll
        for (int ni = 0; ni < 8; ni++)
            #pragma unroll
            for (int r = 0; r < 4; r++) acc[mi][ni][r] = 0.f;

    for (int k0 = 0; k0 < K; k0 += BK) {
        #pragma unroll
        for (int l = 0; l < 4; l++) {
            int idx = tid + l * 256;        // 0..1023
            int row = idx >> 3;             // 0..127
            int c4  = (idx & 7) * 4;        // 0,4,...,28
            float4 av = *(const float4*)(A + (long)(m0 + row) * K + k0 + c4);
            float4 bv = *(const float4*)(B + (long)(n0 + row) * K + k0 + c4);
            uint4 at, bt;
            at.x = f2tf32(av.x); at.y = f2tf32(av.y);
            at.z = f2tf32(av.z); at.w = f2tf32(av.w);
            bt.x = f2tf32(bv.x); bt.y = f2tf32(bv.y);
            bt.z = f2tf32(bv.z); bt.w = f2tf32(bv.w);
            *(uint4*)&As[row * PIT + c4] = at;
            *(uint4*)&Bs[row * PIT + c4] = bt;
        }
        __syncthreads();

        #pragma unroll
        for (int ks = 0; ks < BK; ks += 8) {
            unsigned a[2][4], b[8][2];
            #pragma unroll
            for (int mi = 0; mi < 2; mi++) {
                int r = wm + mi * 16;
                a[mi][0] = As[(r + g)     * PIT + ks + c];
                a[mi][1] = As[(r + 8 + g) * PIT + ks + c];
                a[mi][2] = As[(r + g)     * PIT + ks + c + 4];
                a[mi][3] = As[(r + 8 + g) * PIT + ks + c + 4];
            }
            #pragma unroll
            for (int ni = 0; ni < 8; ni++) {
                b[ni][0] = Bs[(wn + ni * 8 + g) * PIT + ks + c];
                b[ni][1] = Bs[(wn + ni * 8 + g) * PIT + ks + c + 4];
            }
            #pragma unroll
            for (int mi = 0; mi < 2; mi++)
                #pragma unroll
                for (int ni = 0; ni < 8; ni++) {
                    asm volatile(
                        "mma.sync.aligned.m16n8k8.row.col.f32.tf32.tf32.f32 "
                        "{%0,%1,%2,%3}, {%4,%5,%6,%7}, {%8,%9}, {%0,%1,%2,%3};"
                        : "+f"(acc[mi][ni][0]), "+f"(acc[mi][ni][1]),
                          "+f"(acc[mi][ni][2]), "+f"(acc[mi][ni][3])
                        : "r"(a[mi][0]), "r"(a[mi][1]), "r"(a[mi][2]), "r"(a[mi][3]),
                          "r"(b[ni][0]), "r"(b[ni][1]));
                }
        }
        __syncthreads();
    }

    #pragma unroll
    for (int mi = 0; mi < 2; mi++) {
        #pragma unroll
        for (int ni = 0; ni < 8; ni++) {
            int row0 = m0 + wm + mi * 16 + g;
            int col  = n0 + wn + ni * 8 + 2 * c;
            *(float2*)&C[(long)row0 * ldc + col] =
                make_float2(acc[mi][ni][0], acc[mi][ni][1]);
            *(float2*)&C[(long)(row0 + 8) * ldc + col] =
                make_float2(acc[mi][ni][2], acc[mi][ni][3]);
        }
    }
}

// ---------------------------------------------------------------------------
// Prep: gate + ve add, RoPE, RMS-norm, rearrange. (unchanged)
// ---------------------------------------------------------------------------
__global__ void prep_kernel(const float* __restrict__ raw,
                            const float* __restrict__ x,
                            const float* __restrict__ ve,
                            const float* __restrict__ cosv,
                            const float* __restrict__ sinv,
                            const float* __restrict__ Wg,
                            float* __restrict__ Q,
                            float* __restrict__ Kd,
                            float* __restrict__ Vd) {
    const int r = blockIdx.x;
    const int b = r >> 10;
    const int t = r & 1023;
    const int w = threadIdx.x >> 5;
    const int lane = threadIdx.x & 31;

    const float c = cosv[t * 32 + lane];
    const float s = sinv[t * 32 + lane];
    const float* row = raw + (long)r * NQKV;
    const float EPS = 1.1920928955078125e-07f;

    #pragma unroll
    for (int hh = 0; hh < 4; hh++) {
        int h = w + hh * 4;
        float x1 = row[h * 64 + lane];
        float x2 = row[h * 64 + 32 + lane];
        float y1 = x1 * c + x2 * s;
        float y2 = -x1 * s + x2 * c;
        float ss = warpSum(y1 * y1 + y2 * y2);
        float rn = rsqrtf(ss * (1.f / 64.f) + EPS) * 1.2f;
        float* qo = Q + ((long)(b * Hq + h) * Tq + t) * 64;
        qo[lane] = y1 * rn;
        qo[lane + 32] = y2 * rn;
    }
    {
        float x1 = row[1024 + w * 64 + lane];
        float x2 = row[1024 + w * 64 + 32 + lane];
        float y1 = x1 * c + x2 * s;
        float y2 = -x1 * s + x2 * c;
        float ss = warpSum(y1 * y1 + y2 * y2);
        float rn = rsqrtf(ss * (1.f / 64.f) + EPS) * 1.2f;
        float* ko = Kd + ((long)(b * HKVq + w) * Tq + t) * 64;
        ko[lane] = y1 * rn;
        ko[lane + 32] = y2 * rn;
    }
    {
        float gv = 0.f;
        if (lane < GATE_CH) gv = x[(long)r * Cq + lane] * Wg[w * GATE_CH + lane];
        gv = warpSum(gv);
        float gate = 3.f / (1.f + __expf(-gv));
        float v1 = row[1280 + w * 64 + lane]      + gate * ve[(long)r * 256 + w * 64 + lane];
        float v2 = row[1280 + w * 64 + 32 + lane] + gate * ve[(long)r * 256 + w * 64 + 32 + lane];
        float* vo = Vd + ((long)(b * HKVq + w) * Tq + t) * 64;
        vo[lane] = v1;
        vo[lane + 32] = v2;
    }
}

// ---------------------------------------------------------------------------
// Sliding-window attention. (unchanged)
// ---------------------------------------------------------------------------
#define QTILE 64
#define KTILE 320
#define KPITCH 65
#define ATTN_SMEM ((2 * KTILE * KPITCH + 8 * KTILE + 8 * 64) * 4)

__global__ void attn_kernel(const float* __restrict__ Q,
                            const float* __restrict__ Kd,
                            const float* __restrict__ Vd,
                            float* __restrict__ Y,
                            const int* __restrict__ wptr) {
    extern __shared__ float sm[];
    float* Ks  = sm;
    float* Vs  = Ks + KTILE * KPITCH;
    float* psm = Vs + KTILE * KPITCH;
    float* qsm = psm + 8 * KTILE;

    const int W = *wptr;
    const int bh = blockIdx.y;
    const int b = bh >> 4;
    const int h = bh & 15;
    const int g = h >> 2;
    const int qt0 = blockIdx.x * QTILE;
    const int ks0 = qt0 - 256;

    const float* Kbase = Kd + (long)(b * HKVq + g) * Tq * 64;
    const float* Vbase = Vd + (long)(b * HKVq + g) * Tq * 64;
    const float* Qbase = Q + (long)bh * Tq * 64;

    for (int idx = threadIdx.x; idx < KTILE * 64; idx += blockDim.x) {
        int jl = idx >> 6, d = idx & 63;
        int jg = ks0 + jl;
        if (jg >= 0) {
            Ks[jl * KPITCH + d] = Kbase[jg * 64 + d];
            Vs[jl * KPITCH + d] = Vbase[jg * 64 + d];
        }
    }
    __syncthreads();

    const int w = threadIdx.x >> 5;
    const int lane = threadIdx.x & 31;
    float* pw = psm + w * KTILE;
    float* qw = qsm + w * 64;

    for (int qq = 0; qq < 8; qq++) {
        const int i = qt0 + w * 8 + qq;
        qw[lane]      = Qbase[i * 64 + lane];
        qw[lane + 32] = Qbase[i * 64 + 32 + lane];
        __syncwarp();

        const int lo = max(0, i - W);
        const int n = i - lo + 1;

        float m = -1e30f;
        for (int jj = lane; jj < n; jj += 32) {
            const float* kr = Ks + (lo + jj - ks0) * KPITCH;
            float sc = 0.f;
            #pragma unroll
            for (int d = 0; d < 64; d++) sc += qw[d] * kr[d];
            sc *= 0.125f;
            pw[jj] = sc;
            m = fmaxf(m, sc);
        }
        m = warpMax(m);

        float sum = 0.f;
        for (int jj = lane; jj < n; jj += 32) {
            float p = __expf(pw[jj] - m);
            pw[jj] = p;
            sum += p;
        }
        sum = warpSum(sum);
        __syncwarp();
        const float inv = 1.f / sum;

        float a0 = 0.f, a1 = 0.f;
        for (int jj = 0; jj < n; jj++) {
            float p = pw[jj];
            const float* vr = Vs + (lo + jj - ks0) * KPITCH;
            a0 += p * vr[lane];
            a1 += p * vr[lane + 32];
        }
        float* yo = Y + ((long)(b * Tq + i) * Cq) + h * 64;
        yo[lane]      = a0 * inv;
        yo[lane + 32] = a1 * inv;
        __syncwarp();
    }
}

// ---------------------------------------------------------------------------
extern "C" void kernel_launch(void* const* d_in, const int* in_sizes, int n_in,
                              void* d_out, int out_size) {
    const float* x    = (const float*)d_in[0];
    const float* ve   = (const float*)d_in[1];
    const float* cosv = (const float*)d_in[2];
    const float* sinv = (const float*)d_in[3];
    const float* Wq   = (const float*)d_in[4];
    const float* Wk   = (const float*)d_in[5];
    const float* Wv   = (const float*)d_in[6];
    const float* Wo   = (const float*)d_in[7];
    const float* Wg   = (const float*)d_in[8];
    const int*   wptr = (const int*)d_in[9];
    float* out = (float*)d_out;

    float *raw, *Q, *K, *V, *Y;
    cudaGetSymbolAddress((void**)&raw, g_raw);
    cudaGetSymbolAddress((void**)&Q, g_Q);
    cudaGetSymbolAddress((void**)&K, g_K);
    cudaGetSymbolAddress((void**)&V, g_V);
    cudaGetSymbolAddress((void**)&Y, g_Y);

    cudaFuncSetAttribute(attn_kernel,
                         cudaFuncAttributeMaxDynamicSharedMemorySize, ATTN_SMEM);

    // QKV projections into raw [4096, 1536]  (tf32 tensor cores)
    gemm_tf32<<<dim3(Hq*Dq/BN,   MROWS/BM), 256>>>(x, Wq, raw,        Cq, NQKV);
    gemm_tf32<<<dim3(HKVq*Dq/BN, MROWS/BM), 256>>>(x, Wk, raw + 1024, Cq, NQKV);
    gemm_tf32<<<dim3(HKVq*Dq/BN, MROWS/BM), 256>>>(x, Wv, raw + 1280, Cq, NQKV);

    // gate/ve/rope/rmsnorm/rearrange
    prep_kernel<<<MROWS, 128>>>(raw, x, ve, cosv, sinv, Wg, Q, K, V);

    // sliding-window attention
    attn_kernel<<<dim3(Tq/QTILE, Bq*Hq), 256, ATTN_SMEM>>>(Q, K, V, Y, wptr);

    // output projection  (tf32 tensor cores)
    gemm_tf32<<<dim3(Cq/BN, MROWS/BM), 256>>>(Y, Wo, out, Cq, Cq);
    (void)in_sizes; (void)n_in; (void)out_size;
}

// round 3
// speedup vs baseline: 4.3410x; 2.4888x over previous
#include <cuda_runtime.h>
#include <cuda_bf16.h>

// Problem constants (fixed-shape benchmark)
#define Bq   4
#define Tq   1024
#define Cq   1024
#define Hq   16
#define HKVq 4
#define Dq   64
#define GATE_CH 12
#define MROWS (Bq*Tq)              // 4096
#define NQKV  (Hq*Dq + 2*HKVq*Dq) // 1536

// Scratch (device globals — no allocation allowed)
__device__ float g_raw[MROWS * NQKV];
__device__ float g_Q[Bq*Hq*Tq*Dq];      // [b,h,t,d]
__device__ float g_K[Bq*HKVq*Tq*Dq];    // [b,g,t,d]
__device__ float g_Vt[Bq*HKVq*Dq*Tq];   // [b,g,d,t]  (transposed V)
__device__ float g_Y[MROWS * Cq];

__device__ __forceinline__ float warpSum(float v) {
    #pragma unroll
    for (int o = 16; o; o >>= 1) v += __shfl_xor_sync(0xFFFFFFFFu, v, o);
    return v;
}
__device__ __forceinline__ unsigned f2tf32(float x) {
    unsigned r;
    asm("cvt.rna.tf32.f32 %0, %1;" : "=r"(r) : "f"(x));
    return r;
}

#define MMA8(acc, A0,A1,A2,A3, B0,B1)                                         \
    asm volatile(                                                             \
        "mma.sync.aligned.m16n8k8.row.col.f32.tf32.tf32.f32 "                 \
        "{%0,%1,%2,%3}, {%4,%5,%6,%7}, {%8,%9}, {%0,%1,%2,%3};"               \
        : "+f"((acc)[0]), "+f"((acc)[1]), "+f"((acc)[2]), "+f"((acc)[3])      \
        : "r"(A0), "r"(A1), "r"(A2), "r"(A3), "r"(B0), "r"(B1))

// ---------------------------------------------------------------------------
// TF32 tensor-core GEMM body: C[128,128] tile of A[M,K] @ B[N,K]^T
// ---------------------------------------------------------------------------
#define BM 128
#define BN 128
#define BK 32
#define PIT 36

__device__ __forceinline__ void gemm_body(
        const float* __restrict__ A, const float* __restrict__ B,
        float* __restrict__ C, int K, int ldc, int m0, int n0b, int n0c) {
    __shared__ __align__(16) unsigned As[BM * PIT];
    __shared__ __align__(16) unsigned Bs[BN * PIT];

    const int tid = threadIdx.x;
    const int wid = tid >> 5, lane = tid & 31;
    const int wm = (wid & 3) * 32;
    const int wn = (wid >> 2) * 64;
    const int g = lane >> 2, c = lane & 3;

    float acc[2][8][4];
    #pragma unroll
    for (int mi = 0; mi < 2; mi++)
        #pragma unroll
        for (int ni = 0; ni < 8; ni++)
            #pragma unroll
            for (int r = 0; r < 4; r++) acc[mi][ni][r] = 0.f;

    for (int k0 = 0; k0 < K; k0 += BK) {
        #pragma unroll
        for (int l = 0; l < 4; l++) {
            int idx = tid + l * 256;
            int row = idx >> 3;
            int c4  = (idx & 7) * 4;
            float4 av = *(const float4*)(A + (long)(m0 + row) * K + k0 + c4);
            float4 bv = *(const float4*)(B + (long)(n0b + row) * K + k0 + c4);
            uint4 at, bt;
            at.x = f2tf32(av.x); at.y = f2tf32(av.y);
            at.z = f2tf32(av.z); at.w = f2tf32(av.w);
            bt.x = f2tf32(bv.x); bt.y = f2tf32(bv.y);
            bt.z = f2tf32(bv.z); bt.w = f2tf32(bv.w);
            *(uint4*)&As[row * PIT + c4] = at;
            *(uint4*)&Bs[row * PIT + c4] = bt;
        }
        __syncthreads();

        #pragma unroll
        for (int ks = 0; ks < BK; ks += 8) {
            unsigned a[2][4], b[8][2];
            #pragma unroll
            for (int mi = 0; mi < 2; mi++) {
                int r = wm + mi * 16;
                a[mi][0] = As[(r + g)     * PIT + ks + c];
                a[mi][1] = As[(r + 8 + g) * PIT + ks + c];
                a[mi][2] = As[(r + g)     * PIT + ks + c + 4];
                a[mi][3] = As[(r + 8 + g) * PIT + ks + c + 4];
            }
            #pragma unroll
            for (int ni = 0; ni < 8; ni++) {
                b[ni][0] = Bs[(wn + ni * 8 + g) * PIT + ks + c];
                b[ni][1] = Bs[(wn + ni * 8 + g) * PIT + ks + c + 4];
            }
            #pragma unroll
            for (int mi = 0; mi < 2; mi++)
                #pragma unroll
                for (int ni = 0; ni < 8; ni++)
                    MMA8(acc[mi][ni], a[mi][0], a[mi][1], a[mi][2], a[mi][3],
                         b[ni][0], b[ni][1]);
        }
        __syncthreads();
    }

    #pragma unroll
    for (int mi = 0; mi < 2; mi++) {
        #pragma unroll
        for (int ni = 0; ni < 8; ni++) {
            int row0 = m0 + wm + mi * 16 + g;
            int col  = n0c + wn + ni * 8 + 2 * c;
            *(float2*)&C[(long)row0 * ldc + col] =
                make_float2(acc[mi][ni][0], acc[mi][ni][1]);
            *(float2*)&C[(long)(row0 + 8) * ldc + col] =
                make_float2(acc[mi][ni][2], acc[mi][ni][3]);
        }
    }
}

__global__ __launch_bounds__(256) void gemm_tf32(
        const float* __restrict__ A, const float* __restrict__ B,
        float* __restrict__ C, int K, int ldc) {
    gemm_body(A, B, C, K, ldc, blockIdx.y * BM, blockIdx.x * BN, blockIdx.x * BN);
}

// Fused QKV projection: one launch, nb selects Wq/Wk/Wv and output columns.
__global__ __launch_bounds__(256) void gemm_qkv(
        const float* __restrict__ A,
        const float* __restrict__ Wq, const float* __restrict__ Wk,
        const float* __restrict__ Wv, float* __restrict__ C) {
    const int nb = blockIdx.x;
    const float* Bp;
    int n0b, n0c;
    if (nb < 8)       { Bp = Wq; n0b = nb * 128;        n0c = n0b; }
    else if (nb < 10) { Bp = Wk; n0b = (nb - 8) * 128;  n0c = 1024 + n0b; }
    else              { Bp = Wv; n0b = (nb - 10) * 128; n0c = 1280 + n0b; }
    gemm_body(A, Bp, C, Cq, NQKV, blockIdx.y * BM, n0b, n0c);
}

// ---------------------------------------------------------------------------
// Prep: gate + ve add, RoPE, RMS-norm, rearrange (+ transposed V).
// ---------------------------------------------------------------------------
__global__ void prep_kernel(const float* __restrict__ raw,
                            const float* __restrict__ x,
                            const float* __restrict__ ve,
                            const float* __restrict__ cosv,
                            const float* __restrict__ sinv,
                            const float* __restrict__ Wg,
                            float* __restrict__ Q,
                            float* __restrict__ Kd,
                            float* __restrict__ Vt) {
    const int r = blockIdx.x;
    const int b = r >> 10;
    const int t = r & 1023;
    const int w = threadIdx.x >> 5;
    const int lane = threadIdx.x & 31;

    const float c = cosv[t * 32 + lane];
    const float s = sinv[t * 32 + lane];
    const float* row = raw + (long)r * NQKV;
    const float EPS = 1.1920928955078125e-07f;

    #pragma unroll
    for (int hh = 0; hh < 4; hh++) {
        int h = w + hh * 4;
        float x1 = row[h * 64 + lane];
        float x2 = row[h * 64 + 32 + lane];
        float y1 = x1 * c + x2 * s;
        float y2 = -x1 * s + x2 * c;
        float ss = warpSum(y1 * y1 + y2 * y2);
        float rn = rsqrtf(ss * (1.f / 64.f) + EPS) * 1.2f;
        float* qo = Q + ((long)(b * Hq + h) * Tq + t) * 64;
        qo[lane] = y1 * rn;
        qo[lane + 32] = y2 * rn;
    }
    {
        float x1 = row[1024 + w * 64 + lane];
        float x2 = row[1024 + w * 64 + 32 + lane];
        float y1 = x1 * c + x2 * s;
        float y2 = -x1 * s + x2 * c;
        float ss = warpSum(y1 * y1 + y2 * y2);
        float rn = rsqrtf(ss * (1.f / 64.f) + EPS) * 1.2f;
        float* ko = Kd + ((long)(b * HKVq + w) * Tq + t) * 64;
        ko[lane] = y1 * rn;
        ko[lane + 32] = y2 * rn;
    }
    {
        float gv = 0.f;
        if (lane < GATE_CH) gv = x[(long)r * Cq + lane] * Wg[w * GATE_CH + lane];
        gv = warpSum(gv);
        float gate = 3.f / (1.f + __expf(-gv));
        float v1 = row[1280 + w * 64 + lane]      + gate * ve[(long)r * 256 + w * 64 + lane];
        float v2 = row[1280 + w * 64 + 32 + lane] + gate * ve[(long)r * 256 + w * 64 + 32 + lane];
        // transposed: Vt[bg][d][t]
        float* vb = Vt + ((long)(b * HKVq + w) * 64) * Tq;
        vb[(long)lane * Tq + t]        = v1;
        vb[(long)(lane + 32) * Tq + t] = v2;
    }
}

// ---------------------------------------------------------------------------
// Tensor-core sliding-window attention (tf32).
// Grid (16, 64): (query tile of 64, b*H+h). 256 threads = 8 warps.
// Warp (kh=wid>>2, mt=wid&3): S rows [mt*16,mt*16+16), keys = 32-blocks with
// (blk32 & 1) == kh  (5 blocks of 32 keys each = 160 keys, 20 mma n-tiles).
// ---------------------------------------------------------------------------
#define KWIN 320
#define KP   68      // K/Q/P smem pitch (words):  banks 4g+c  -> conflict-free
#define VTP  324     // Vt smem pitch: 324 % 32 == 4           -> conflict-free
#define SM_Q   0
#define SM_K   (SM_Q + 64 * KP)           // 4352
#define SM_VT  (SM_K + KWIN * KP)         // +21760
#define SM_P   (SM_VT + 64 * VTP)         // +20736
#define SM_ST  (SM_P + 64 * KP)           // +4352
#define ATTN_WORDS (SM_ST + 256)
#define ATTN_SMEM  (ATTN_WORDS * 4)

__global__ __launch_bounds__(256) void attn_mma(
        const float* __restrict__ Q, const float* __restrict__ Kd,
        const float* __restrict__ Vt, float* __restrict__ Y,
        const int* __restrict__ wptr) {
    extern __shared__ unsigned sm[];
    unsigned* Qs  = sm + SM_Q;
    unsigned* Ks  = sm + SM_K;
    unsigned* Vts = sm + SM_VT;
    unsigned* Ps  = sm + SM_P;
    float* smax = (float*)(sm + SM_ST);        // [2][64]
    float* ssum = smax + 128;                  // [2][64]

    const int W = *wptr;
    const int bh = blockIdx.y;
    const int b = bh >> 4;
    const int h = bh & 15;
    const int bg = (b << 2) | (h >> 2);
    const int qt0 = blockIdx.x * 64;
    const int ks0 = qt0 - 256;

    const int tid = threadIdx.x;
    const int wid = tid >> 5, lane = tid & 31;
    const int kh = wid >> 2, mt = wid & 3;
    const int g = lane >> 2, c = lane & 3;

    const float* Qb  = Q  + (long)bh * Tq * 64;
    const float* Kb  = Kd + (long)bg * Tq * 64;
    const float* Vtb = Vt + (long)bg * 64 * Tq;

    // ---- loads (tf32 convert at store) ----
    #pragma unroll
    for (int r = 0; r < 8; r++) {                 // Q rows wid*8+r
        int q = wid * 8 + r;
        float2 v = *(const float2*)(Qb + (long)(qt0 + q) * 64 + lane * 2);
        Qs[q * KP + lane * 2]     = f2tf32(v.x);
        Qs[q * KP + lane * 2 + 1] = f2tf32(v.y);
    }
    #pragma unroll
    for (int r = 0; r < 40; r++) {                // K rows wid*40+r
        int jl = wid * 40 + r;
        int jg = min(max(ks0 + jl, 0), Tq - 1);
        float2 v = *(const float2*)(Kb + (long)jg * 64 + lane * 2);
        Ks[jl * KP + lane * 2]     = f2tf32(v.x);
        Ks[jl * KP + lane * 2 + 1] = f2tf32(v.y);
    }
    #pragma unroll
    for (int r = 0; r < 8; r++) {                 // Vt rows (d) wid*8+r
        int d = wid * 8 + r;
        #pragma unroll
        for (int j = 0; j < KWIN; j += 32) {
            int jg = min(max(ks0 + j + lane, 0), Tq - 1);
            Vts[d * VTP + j + lane] = f2tf32(Vtb[(long)d * Tq + jg]);
        }
    }
    __syncthreads();

    // ---- S = Q @ K^T ----
    float S[20][4];
    #pragma unroll
    for (int nt = 0; nt < 20; nt++)
        #pragma unroll
        for (int r = 0; r < 4; r++) S[nt][r] = 0.f;

    const int q0 = mt * 16;
    #pragma unroll
    for (int ks = 0; ks < 8; ks++) {
        unsigned a0 = Qs[(q0 + g)     * KP + ks * 8 + c];
        unsigned a1 = Qs[(q0 + 8 + g) * KP + ks * 8 + c];
        unsigned a2 = Qs[(q0 + g)     * KP + ks * 8 + c + 4];
        unsigned a3 = Qs[(q0 + 8 + g) * KP + ks * 8 + c + 4];
        #pragma unroll
        for (int nt = 0; nt < 20; nt++) {
            int key0 = ((nt >> 2) * 2 + kh) * 32 + (nt & 3) * 8;
            unsigned b0 = Ks[(key0 + g) * KP + ks * 8 + c];
            unsigned b1 = Ks[(key0 + g) * KP + ks * 8 + c + 4];
            MMA8(S[nt], a0, a1, a2, a3, b0, b1);
        }
    }

    // ---- scale + mask + row max ----
    const int i0 = qt0 + q0 + g, i1 = i0 + 8;
    float mx0 = -1e30f, mx1 = -1e30f;
    #pragma unroll
    for (int nt = 0; nt < 20; nt++) {
        int key0 = ((nt >> 2) * 2 + kh) * 32 + (nt & 3) * 8;
        int j0 = ks0 + key0 + 2 * c, j1 = j0 + 1;
        S[nt][0] = (j0 >= 0 && j0 <= i0 && (i0 - j0) <= W) ? S[nt][0] * 0.125f : -1e30f;
        S[nt][1] = (j1 >= 0 && j1 <= i0 && (i0 - j1) <= W) ? S[nt][1] * 0.125f : -1e30f;
        S[nt][2] = (j0 >= 0 && j0 <= i1 && (i1 - j0) <= W) ? S[nt][2] * 0.125f : -1e30f;
        S[nt][3] = (j1 >= 0 && j1 <= i1 && (i1 - j1) <= W) ? S[nt][3] * 0.125f : -1e30f;
        mx0 = fmaxf(mx0, fmaxf(S[nt][0], S[nt][1]));
        mx1 = fmaxf(mx1, fmaxf(S[nt][2], S[nt][3]));
    }
    #pragma unroll
    for (int o = 1; o < 4; o <<= 1) {
        mx0 = fmaxf(mx0, __shfl_xor_sync(0xFFFFFFFFu, mx0, o));
        mx1 = fmaxf(mx1, __shfl_xor_sync(0xFFFFFFFFu, mx1, o));
    }
    if (c == 0) {
        smax[kh * 64 + q0 + g]     = mx0;
        smax[kh * 64 + q0 + g + 8] = mx1;
    }
    __syncthreads();
    const float m0 = fmaxf(smax[q0 + g],     smax[64 + q0 + g]);
    const float m1 = fmaxf(smax[q0 + g + 8], smax[64 + q0 + g + 8]);

    // ---- exp + row sum ----
    float s0 = 0.f, s1 = 0.f;
    #pragma unroll
    for (int nt = 0; nt < 20; nt++) {
        S[nt][0] = __expf(S[nt][0] - m0);
        S[nt][1] = __expf(S[nt][1] - m0);
        S[nt][2] = __expf(S[nt][2] - m1);
        S[nt][3] = __expf(S[nt][3] - m1);
        s0 += S[nt][0] + S[nt][1];
        s1 += S[nt][2] + S[nt][3];
    }
    #pragma unroll
    for (int o = 1; o < 4; o <<= 1) {
        s0 += __shfl_xor_sync(0xFFFFFFFFu, s0, o);
        s1 += __shfl_xor_sync(0xFFFFFFFFu, s1, o);
    }
    if (c == 0) {
        ssum[kh * 64 + q0 + g]     = s0;
        ssum[kh * 64 + q0 + g + 8] = s1;
    }

    // ---- O = P @ V (chunks of 64 keys via smem staging) ----
    float O[4][4];
    #pragma unroll
    for (int nd = 0; nd < 4; nd++)
        #pragma unroll
        for (int r = 0; r < 4; r++) O[nd][r] = 0.f;
    const int oh = kh;   // this warp's d-half for O

    #pragma unroll
    for (int ck = 0; ck < 5; ck++) {
        __syncthreads();
        // stage this chunk: my tiles nt = 4*ck .. 4*ck+3 -> cols kh*32 + (nt&3)*8
        #pragma unroll
        for (int j = 0; j < 4; j++) {
            int nt = 4 * ck + j;
            int colb = kh * 32 + j * 8;
            Ps[(q0 + g)     * KP + colb + 2 * c]     = f2tf32(S[nt][0]);
            Ps[(q0 + g)     * KP + colb + 2 * c + 1] = f2tf32(S[nt][1]);
            Ps[(q0 + g + 8) * KP + colb + 2 * c]     = f2tf32(S[nt][2]);
            Ps[(q0 + g + 8) * KP + colb + 2 * c + 1] = f2tf32(S[nt][3]);
        }
        __syncthreads();
        #pragma unroll
        for (int ks = 0; ks < 8; ks++) {
            unsigned a0 = Ps[(q0 + g)     * KP + ks * 8 + c];
            unsigned a1 = Ps[(q0 + 8 + g) * KP + ks * 8 + c];
            unsigned a2 = Ps[(q0 + g)     * KP + ks * 8 + c + 4];
            unsigned a3 = Ps[(q0 + 8 + g) * KP + ks * 8 + c + 4];
            int kb = ck * 64 + ks * 8;
            #pragma unroll
            for (int nd = 0; nd < 4; nd++) {
                int d0 = oh * 32 + nd * 8;
                unsigned b0 = Vts[(d0 + g) * VTP + kb + c];
                unsigned b1 = Vts[(d0 + g) * VTP + kb + c + 4];
                MMA8(O[nd], a0, a1, a2, a3, b0, b1);
            }
        }
    }
    __syncthreads();

    // ---- normalize + store ----
    const float inv0 = 1.f / (ssum[q0 + g]     + ssum[64 + q0 + g]);
    const float inv1 = 1.f / (ssum[q0 + g + 8] + ssum[64 + q0 + g + 8]);
    const int row0 = qt0 + q0 + g;
    #pragma unroll
    for (int nd = 0; nd < 4; nd++) {
        int col = h * 64 + oh * 32 + nd * 8 + 2 * c;
        *(float2*)&Y[((long)(b * Tq + row0) * Cq) + col] =
            make_float2(O[nd][0] * inv0, O[nd][1] * inv0);
        *(float2*)&Y[((long)(b * Tq + row0 + 8) * Cq) + col] =
            make_float2(O[nd][2] * inv1, O[nd][3] * inv1);
    }
}

// ---------------------------------------------------------------------------
extern "C" void kernel_launch(void* const* d_in, const int* in_sizes, int n_in,
                              void* d_out, int out_size) {
    const float* x    = (const float*)d_in[0];
    const float* ve   = (const float*)d_in[1];
    const float* cosv = (const float*)d_in[2];
    const float* sinv = (const float*)d_in[3];
    const float* Wq   = (const float*)d_in[4];
    const float* Wk   = (const float*)d_in[5];
    const float* Wv   = (const float*)d_in[6];
    const float* Wo   = (const float*)d_in[7];
    const float* Wg   = (const float*)d_in[8];
    const int*   wptr = (const int*)d_in[9];
    float* out = (float*)d_out;

    float *raw, *Q, *K, *Vt, *Y;
    cudaGetSymbolAddress((void**)&raw, g_raw);
    cudaGetSymbolAddress((void**)&Q, g_Q);
    cudaGetSymbolAddress((void**)&K, g_K);
    cudaGetSymbolAddress((void**)&Vt, g_Vt);
    cudaGetSymbolAddress((void**)&Y, g_Y);

    cudaFuncSetAttribute(attn_mma,
                         cudaFuncAttributeMaxDynamicSharedMemorySize, ATTN_SMEM);

    // fused QKV projection (tf32 tensor cores)
    gemm_qkv<<<dim3(12, MROWS/BM), 256>>>(x, Wq, Wk, Wv, raw);

    // gate/ve/rope/rmsnorm/rearrange (+V transpose)
    prep_kernel<<<MROWS, 128>>>(raw, x, ve, cosv, sinv, Wg, Q, K, Vt);

    // tensor-core sliding-window attention
    attn_mma<<<dim3(Tq/64, Bq*Hq), 256, ATTN_SMEM>>>(Q, K, Vt, Y, wptr);

    // output projection (tf32 tensor cores)
    gemm_tf32<<<dim3(Cq/BN, MROWS/BM), 256>>>(Y, Wo, out, Cq, Cq);
    (void)in_sizes; (void)n_in; (void)out_size;
}

// round 5
// speedup vs baseline: 4.4731x; 1.0304x over previous
#include <cuda_runtime.h>
#include <cuda_bf16.h>

// Problem constants (fixed-shape benchmark)
#define Bq   4
#define Tq   1024
#define Cq   1024
#define Hq   16
#define HKVq 4
#define Dq   64
#define GATE_CH 12
#define MROWS (Bq*Tq)              // 4096
#define NQKV  (Hq*Dq + 2*HKVq*Dq) // 1536

// Scratch (device globals — no allocation allowed)
__device__ float g_raw[MROWS * NQKV];
__device__ float g_Q[Bq*Hq*Tq*Dq];      // [b,h,t,d]
__device__ float g_K[Bq*HKVq*Tq*Dq];    // [b,g,t,d]
__device__ float g_Vt[Bq*HKVq*Dq*Tq];   // [b,g,d,t]  (transposed V)
__device__ float g_Y[MROWS * Cq];

__device__ __forceinline__ float warpSum(float v) {
    #pragma unroll
    for (int o = 16; o; o >>= 1) v += __shfl_xor_sync(0xFFFFFFFFu, v, o);
    return v;
}
__device__ __forceinline__ unsigned f2tf32(float x) {
    unsigned r;
    asm("cvt.rna.tf32.f32 %0, %1;" : "=r"(r) : "f"(x));
    return r;
}

#define MMA8(acc, A0,A1,A2,A3, B0,B1)                                         \
    asm volatile(                                                             \
        "mma.sync.aligned.m16n8k8.row.col.f32.tf32.tf32.f32 "                 \
        "{%0,%1,%2,%3}, {%4,%5,%6,%7}, {%8,%9}, {%0,%1,%2,%3};"               \
        : "+f"((acc)[0]), "+f"((acc)[1]), "+f"((acc)[2]), "+f"((acc)[3])      \
        : "r"(A0), "r"(A1), "r"(A2), "r"(A3), "r"(B0), "r"(B1))

// ---------------------------------------------------------------------------
// TF32 tensor-core GEMM, cp.async double-buffered.
// C[128,128] tile of A[M,K] @ B[N,K]^T. 256 threads, 8 warps (32x64 each).
// Dynamic smem: 2 stages x (As[128*36] + Bs[128*36]) floats = 73728 B.
// ---------------------------------------------------------------------------
#define BM 128
#define BN 128
#define BK 32
#define PIT 36
#define GEMM_SMEM (2 * (BM + BN) * PIT * 4)

__device__ __forceinline__ void cp16(float* dst, const float* src) {
    unsigned d = (unsigned)__cvta_generic_to_shared(dst);
    asm volatile("cp.async.ca.shared.global [%0], [%1], 16;" :: "r"(d), "l"(src));
}

__device__ __forceinline__ void gemm_body(
        const float* __restrict__ A, const float* __restrict__ B,
        float* __restrict__ C, int K, int ldc, int m0, int n0b, int n0c,
        float* sA, float* sB) {
    const int tid = threadIdx.x;
    const int wid = tid >> 5, lane = tid & 31;
    const int wm = (wid & 3) * 32;
    const int wn = (wid >> 2) * 64;
    const int g = lane >> 2, c = lane & 3;

    const int lrow = tid >> 3;          // 0..31 rows per 256-thread pass
    const int lc4  = (tid & 7) * 4;

    float acc[2][8][4];
    #pragma unroll
    for (int mi = 0; mi < 2; mi++)
        #pragma unroll
        for (int ni = 0; ni < 8; ni++)
            #pragma unroll
            for (int r = 0; r < 4; r++) acc[mi][ni][r] = 0.f;

    // async stage loader
    #define ISSUE(st, k0)                                                     \
        do {                                                                  \
            _Pragma("unroll")                                                 \
            for (int l = 0; l < 4; l++) {                                     \
                int row = lrow + l * 32;                                      \
                cp16(sA + (st) * BM * PIT + row * PIT + lc4,                  \
                     A + (long)(m0 + row) * K + (k0) + lc4);                  \
                cp16(sB + (st) * BN * PIT + row * PIT + lc4,                  \
                     B + (long)(n0b + row) * K + (k0) + lc4);                 \
            }                                                                 \
            asm volatile("cp.async.commit_group;");                           \
        } while (0)

    ISSUE(0, 0);
    const int NIT = K / BK;
    for (int it = 0; it < NIT; it++) {
        if (it + 1 < NIT) {
            ISSUE((it + 1) & 1, (it + 1) * BK);
            asm volatile("cp.async.wait_group 1;");
        } else {
            asm volatile("cp.async.wait_group 0;");
        }
        __syncthreads();
        const float* As = sA + (it & 1) * BM * PIT;
        const float* Bs = sB + (it & 1) * BN * PIT;

        #pragma unroll
        for (int ks = 0; ks < BK; ks += 8) {
            unsigned a[2][4], b[8][2];
            #pragma unroll
            for (int mi = 0; mi < 2; mi++) {
                int r = wm + mi * 16;
                a[mi][0] = f2tf32(As[(r + g)     * PIT + ks + c]);
                a[mi][1] = f2tf32(As[(r + 8 + g) * PIT + ks + c]);
                a[mi][2] = f2tf32(As[(r + g)     * PIT + ks + c + 4]);
                a[mi][3] = f2tf32(As[(r + 8 + g) * PIT + ks + c + 4]);
            }
            #pragma unroll
            for (int ni = 0; ni < 8; ni++) {
                b[ni][0] = f2tf32(Bs[(wn + ni * 8 + g) * PIT + ks + c]);
                b[ni][1] = f2tf32(Bs[(wn + ni * 8 + g) * PIT + ks + c + 4]);
            }
            #pragma unroll
            for (int mi = 0; mi < 2; mi++)
                #pragma unroll
                for (int ni = 0; ni < 8; ni++)
                    MMA8(acc[mi][ni], a[mi][0], a[mi][1], a[mi][2], a[mi][3],
                         b[ni][0], b[ni][1]);
        }
        __syncthreads();
    }
    #undef ISSUE

    #pragma unroll
    for (int mi = 0; mi < 2; mi++) {
        #pragma unroll
        for (int ni = 0; ni < 8; ni++) {
            int row0 = m0 + wm + mi * 16 + g;
            int col  = n0c + wn + ni * 8 + 2 * c;
            *(float2*)&C[(long)row0 * ldc + col] =
                make_float2(acc[mi][ni][0], acc[mi][ni][1]);
            *(float2*)&C[(long)(row0 + 8) * ldc + col] =
                make_float2(acc[mi][ni][2], acc[mi][ni][3]);
        }
    }
}

__global__ __launch_bounds__(256, 2) void gemm_tf32(
        const float* __restrict__ A, const float* __restrict__ B,
        float* __restrict__ C, int K, int ldc) {
    extern __shared__ float smem[];
    gemm_body(A, B, C, K, ldc, blockIdx.y * BM, blockIdx.x * BN, blockIdx.x * BN,
              smem, smem + 2 * BM * PIT);
}

__global__ __launch_bounds__(256, 2) void gemm_qkv(
        const float* __restrict__ A,
        const float* __restrict__ Wq, const float* __restrict__ Wk,
        const float* __restrict__ Wv, float* __restrict__ C) {
    extern __shared__ float smem[];
    const int nb = blockIdx.x;
    const float* Bp;
    int n0b, n0c;
    if (nb < 8)       { Bp = Wq; n0b = nb * 128;        n0c = n0b; }
    else if (nb < 10) { Bp = Wk; n0b = (nb - 8) * 128;  n0c = 1024 + n0b; }
    else              { Bp = Wv; n0b = (nb - 10) * 128; n0c = 1280 + n0b; }
    gemm_body(A, Bp, C, Cq, NQKV, blockIdx.y * BM, n0b, n0c,
              smem, smem + 2 * BM * PIT);
}

// ---------------------------------------------------------------------------
// Prep: gate + ve add, RoPE, RMS-norm, rearrange (+ transposed V).
// ---------------------------------------------------------------------------
__global__ void prep_kernel(const float* __restrict__ raw,
                            const float* __restrict__ x,
                            const float* __restrict__ ve,
                            const float* __restrict__ cosv,
                            const float* __restrict__ sinv,
                            const float* __restrict__ Wg,
                            float* __restrict__ Q,
                            float* __restrict__ Kd,
                            float* __restrict__ Vt) {
    const int r = blockIdx.x;
    const int b = r >> 10;
    const int t = r & 1023;
    const int w = threadIdx.x >> 5;
    const int lane = threadIdx.x & 31;

    const float c = cosv[t * 32 + lane];
    const float s = sinv[t * 32 + lane];
    const float* row = raw + (long)r * NQKV;
    const float EPS = 1.1920928955078125e-07f;

    #pragma unroll
    for (int hh = 0; hh < 4; hh++) {
        int h = w + hh * 4;
        float x1 = row[h * 64 + lane];
        float x2 = row[h * 64 + 32 + lane];
        float y1 = x1 * c + x2 * s;
        float y2 = -x1 * s + x2 * c;
        float ss = warpSum(y1 * y1 + y2 * y2);
        float rn = rsqrtf(ss * (1.f / 64.f) + EPS) * 1.2f;
        float* qo = Q + ((long)(b * Hq + h) * Tq + t) * 64;
        qo[lane] = y1 * rn;
        qo[lane + 32] = y2 * rn;
    }
    {
        float x1 = row[1024 + w * 64 + lane];
        float x2 = row[1024 + w * 64 + 32 + lane];
        float y1 = x1 * c + x2 * s;
        float y2 = -x1 * s + x2 * c;
        float ss = warpSum(y1 * y1 + y2 * y2);
        float rn = rsqrtf(ss * (1.f / 64.f) + EPS) * 1.2f;
        float* ko = Kd + ((long)(b * HKVq + w) * Tq + t) * 64;
        ko[lane] = y1 * rn;
        ko[lane + 32] = y2 * rn;
    }
    {
        float gv = 0.f;
        if (lane < GATE_CH) gv = x[(long)r * Cq + lane] * Wg[w * GATE_CH + lane];
        gv = warpSum(gv);
        float gate = 3.f / (1.f + __expf(-gv));
        float v1 = row[1280 + w * 64 + lane]      + gate * ve[(long)r * 256 + w * 64 + lane];
        float v2 = row[1280 + w * 64 + 32 + lane] + gate * ve[(long)r * 256 + w * 64 + 32 + lane];
        float* vb = Vt + ((long)(b * HKVq + w) * 64) * Tq;
        vb[(long)lane * Tq + t]        = v1;
        vb[(long)(lane + 32) * Tq + t] = v2;
    }
}

// ---------------------------------------------------------------------------
// Tensor-core sliding-window attention (tf32).
// ---------------------------------------------------------------------------
#define KWIN 320
#define KP   68
#define VTP  324
#define SM_Q   0
#define SM_K   (SM_Q + 64 * KP)
#define SM_VT  (SM_K + KWIN * KP)
#define SM_P   (SM_VT + 64 * VTP)
#define SM_ST  (SM_P + 64 * KP)
#define ATTN_WORDS (SM_ST + 256)
#define ATTN_SMEM  (ATTN_WORDS * 4)

__global__ __launch_bounds__(256) void attn_mma(
        const float* __restrict__ Q, const float* __restrict__ Kd,
        const float* __restrict__ Vt, float* __restrict__ Y,
        const int* __restrict__ wptr) {
    extern __shared__ unsigned sm[];
    unsigned* Qs  = sm + SM_Q;
    unsigned* Ks  = sm + SM_K;
    unsigned* Vts = sm + SM_VT;
    unsigned* Ps  = sm + SM_P;
    float* smax = (float*)(sm + SM_ST);
    float* ssum = smax + 128;

    const int W = *wptr;
    const int bh = blockIdx.y;
    const int b = bh >> 4;
    const int h = bh & 15;
    const int bg = (b << 2) | (h >> 2);
    const int qt0 = blockIdx.x * 64;
    const int ks0 = qt0 - 256;

    const int tid = threadIdx.x;
    const int wid = tid >> 5, lane = tid & 31;
    const int kh = wid >> 2, mt = wid & 3;
    const int g = lane >> 2, c = lane & 3;

    const float* Qb  = Q  + (long)bh * Tq * 64;
    const float* Kb  = Kd + (long)bg * Tq * 64;
    const float* Vtb = Vt + (long)bg * 64 * Tq;

    #pragma unroll
    for (int r = 0; r < 8; r++) {
        int q = wid * 8 + r;
        float2 v = *(const float2*)(Qb + (long)(qt0 + q) * 64 + lane * 2);
        Qs[q * KP + lane * 2]     = f2tf32(v.x);
        Qs[q * KP + lane * 2 + 1] = f2tf32(v.y);
    }
    #pragma unroll
    for (int r = 0; r < 40; r++) {
        int jl = wid * 40 + r;
        int jg = min(max(ks0 + jl, 0), Tq - 1);
        float2 v = *(const float2*)(Kb + (long)jg * 64 + lane * 2);
        Ks[jl * KP + lane * 2]     = f2tf32(v.x);
        Ks[jl * KP + lane * 2 + 1] = f2tf32(v.y);
    }
    #pragma unroll
    for (int r = 0; r < 8; r++) {
        int d = wid * 8 + r;
        #pragma unroll
        for (int j = 0; j < KWIN; j += 32) {
            int jg = min(max(ks0 + j + lane, 0), Tq - 1);
            Vts[d * VTP + j + lane] = f2tf32(Vtb[(long)d * Tq + jg]);
        }
    }
    __syncthreads();

    float S[20][4];
    #pragma unroll
    for (int nt = 0; nt < 20; nt++)
        #pragma unroll
        for (int r = 0; r < 4; r++) S[nt][r] = 0.f;

    const int q0 = mt * 16;
    #pragma unroll
    for (int ks = 0; ks < 8; ks++) {
        unsigned a0 = Qs[(q0 + g)     * KP + ks * 8 + c];
        unsigned a1 = Qs[(q0 + 8 + g) * KP + ks * 8 + c];
        unsigned a2 = Qs[(q0 + g)     * KP + ks * 8 + c + 4];
        unsigned a3 = Qs[(q0 + 8 + g) * KP + ks * 8 + c + 4];
        #pragma unroll
        for (int nt = 0; nt < 20; nt++) {
            int key0 = ((nt >> 2) * 2 + kh) * 32 + (nt & 3) * 8;
            unsigned b0 = Ks[(key0 + g) * KP + ks * 8 + c];
            unsigned b1 = Ks[(key0 + g) * KP + ks * 8 + c + 4];
            MMA8(S[nt], a0, a1, a2, a3, b0, b1);
        }
    }

    const int i0 = qt0 + q0 + g, i1 = i0 + 8;
    float mx0 = -1e30f, mx1 = -1e30f;
    #pragma unroll
    for (int nt = 0; nt < 20; nt++) {
        int key0 = ((nt >> 2) * 2 + kh) * 32 + (nt & 3) * 8;
        int j0 = ks0 + key0 + 2 * c, j1 = j0 + 1;
        S[nt][0] = (j0 >= 0 && j0 <= i0 && (i0 - j0) <= W) ? S[nt][0] * 0.125f : -1e30f;
        S[nt][1] = (j1 >= 0 && j1 <= i0 && (i0 - j1) <= W) ? S[nt][1] * 0.125f : -1e30f;
        S[nt][2] = (j0 >= 0 && j0 <= i1 && (i1 - j0) <= W) ? S[nt][2] * 0.125f : -1e30f;
        S[nt][3] = (j1 >= 0 && j1 <= i1 && (i1 - j1) <= W) ? S[nt][3] * 0.125f : -1e30f;
        mx0 = fmaxf(mx0, fmaxf(S[nt][0], S[nt][1]));
        mx1 = fmaxf(mx1, fmaxf(S[nt][2], S[nt][3]));
    }
    #pragma unroll
    for (int o = 1; o < 4; o <<= 1) {
        mx0 = fmaxf(mx0, __shfl_xor_sync(0xFFFFFFFFu, mx0, o));
        mx1 = fmaxf(mx1, __shfl_xor_sync(0xFFFFFFFFu, mx1, o));
    }
    if (c == 0) {
        smax[kh * 64 + q0 + g]     = mx0;
        smax[kh * 64 + q0 + g + 8] = mx1;
    }
    __syncthreads();
    const float m0 = fmaxf(smax[q0 + g],     smax[64 + q0 + g]);
    const float m1 = fmaxf(smax[q0 + g + 8], smax[64 + q0 + g + 8]);

    float s0 = 0.f, s1 = 0.f;
    #pragma unroll
    for (int nt = 0; nt < 20; nt++) {
        S[nt][0] = __expf(S[nt][0] - m0);
        S[nt][1] = __expf(S[nt][1] - m0);
        S[nt][2] = __expf(S[nt][2] - m1);
        S[nt][3] = __expf(S[nt][3] - m1);
        s0 += S[nt][0] + S[nt][1];
        s1 += S[nt][2] + S[nt][3];
    }
    #pragma unroll
    for (int o = 1; o < 4; o <<= 1) {
        s0 += __shfl_xor_sync(0xFFFFFFFFu, s0, o);
        s1 += __shfl_xor_sync(0xFFFFFFFFu, s1, o);
    }
    if (c == 0) {
        ssum[kh * 64 + q0 + g]     = s0;
        ssum[kh * 64 + q0 + g + 8] = s1;
    }

    float O[4][4];
    #pragma unroll
    for (int nd = 0; nd < 4; nd++)
        #pragma unroll
        for (int r = 0; r < 4; r++) O[nd][r] = 0.f;
    const int oh = kh;

    #pragma unroll
    for (int ck = 0; ck < 5; ck++) {
        __syncthreads();
        #pragma unroll
        for (int j = 0; j < 4; j++) {
            int nt = 4 * ck + j;
            int colb = kh * 32 + j * 8;
            Ps[(q0 + g)     * KP + colb + 2 * c]     = f2tf32(S[nt][0]);
            Ps[(q0 + g)     * KP + colb + 2 * c + 1] = f2tf32(S[nt][1]);
            Ps[(q0 + g + 8) * KP + colb + 2 * c]     = f2tf32(S[nt][2]);
            Ps[(q0 + g + 8) * KP + colb + 2 * c + 1] = f2tf32(S[nt][3]);
        }
        __syncthreads();
        #pragma unroll
        for (int ks = 0; ks < 8; ks++) {
            unsigned a0 = Ps[(q0 + g)     * KP + ks * 8 + c];
            unsigned a1 = Ps[(q0 + 8 + g) * KP + ks * 8 + c];
            unsigned a2 = Ps[(q0 + g)     * KP + ks * 8 + c + 4];
            unsigned a3 = Ps[(q0 + 8 + g) * KP + ks * 8 + c + 4];
            int kb = ck * 64 + ks * 8;
            #pragma unroll
            for (int nd = 0; nd < 4; nd++) {
                int d0 = oh * 32 + nd * 8;
                unsigned b0 = Vts[(d0 + g) * VTP + kb + c];
                unsigned b1 = Vts[(d0 + g) * VTP + kb + c + 4];
                MMA8(O[nd], a0, a1, a2, a3, b0, b1);
            }
        }
    }
    __syncthreads();

    const float inv0 = 1.f / (ssum[q0 + g]     + ssum[64 + q0 + g]);
    const float inv1 = 1.f / (ssum[q0 + g + 8] + ssum[64 + q0 + g + 8]);
    const int row0 = qt0 + q0 + g;
    #pragma unroll
    for (int nd = 0; nd < 4; nd++) {
        int col = h * 64 + oh * 32 + nd * 8 + 2 * c;
        *(float2*)&Y[((long)(b * Tq + row0) * Cq) + col] =
            make_float2(O[nd][0] * inv0, O[nd][1] * inv0);
        *(float2*)&Y[((long)(b * Tq + row0 + 8) * Cq) + col] =
            make_float2(O[nd][2] * inv1, O[nd][3] * inv1);
    }
}

// ---------------------------------------------------------------------------
extern "C" void kernel_launch(void* const* d_in, const int* in_sizes, int n_in,
                              void* d_out, int out_size) {
    const float* x    = (const float*)d_in[0];
    const float* ve   = (const float*)d_in[1];
    const float* cosv = (const float*)d_in[2];
    const float* sinv = (const float*)d_in[3];
    const float* Wq   = (const float*)d_in[4];
    const float* Wk   = (const float*)d_in[5];
    const float* Wv   = (const float*)d_in[6];
    const float* Wo   = (const float*)d_in[7];
    const float* Wg   = (const float*)d_in[8];
    const int*   wptr = (const int*)d_in[9];
    float* out = (float*)d_out;

    float *raw, *Q, *K, *Vt, *Y;
    cudaGetSymbolAddress((void**)&raw, g_raw);
    cudaGetSymbolAddress((void**)&Q, g_Q);
    cudaGetSymbolAddress((void**)&K, g_K);
    cudaGetSymbolAddress((void**)&Vt, g_Vt);
    cudaGetSymbolAddress((void**)&Y, g_Y);

    cudaFuncSetAttribute(attn_mma,
                         cudaFuncAttributeMaxDynamicSharedMemorySize, ATTN_SMEM);
    cudaFuncSetAttribute(gemm_tf32,
                         cudaFuncAttributeMaxDynamicSharedMemorySize, GEMM_SMEM);
    cudaFuncSetAttribute(gemm_qkv,
                         cudaFuncAttributeMaxDynamicSharedMemorySize, GEMM_SMEM);

    // fused QKV projection (tf32 tensor cores, cp.async pipelined)
    gemm_qkv<<<dim3(12, MROWS/BM), 256, GEMM_SMEM>>>(x, Wq, Wk, Wv, raw);

    // gate/ve/rope/rmsnorm/rearrange (+V transpose)
    prep_kernel<<<MROWS, 128>>>(raw, x, ve, cosv, sinv, Wg, Q, K, Vt);

    // tensor-core sliding-window attention
    attn_mma<<<dim3(Tq/64, Bq*Hq), 256, ATTN_SMEM>>>(Q, K, Vt, Y, wptr);

    // output projection (tf32 tensor cores, cp.async pipelined)
    gemm_tf32<<<dim3(Cq/BN, MROWS/BM), 256, GEMM_SMEM>>>(Y, Wo, out, Cq, Cq);
    (void)in_sizes; (void)n_in; (void)out_size;
}

// round 8
// speedup vs baseline: 4.8262x; 1.0789x over previous
#include <cuda_runtime.h>
#include <cuda_bf16.h>

// Problem constants (fixed-shape benchmark)
#define Bq   4
#define Tq   1024
#define Cq   1024
#define Hq   16
#define HKVq 4
#define Dq   64
#define GATE_CH 12
#define MROWS (Bq*Tq)              // 4096
#define NQKV  (Hq*Dq + 2*HKVq*Dq) // 1536

// Scratch (device globals — no allocation allowed)
__device__ float g_raw[MROWS * NQKV];
__device__ float g_Q[Bq*Hq*Tq*Dq];      // [b,h,t,d]
__device__ float g_K[Bq*HKVq*Tq*Dq];    // [b,g,t,d]
__device__ float g_Vt[Bq*HKVq*Dq*Tq];   // [b,g,d,t]  (transposed V)
__device__ float g_Y[MROWS * Cq];

__device__ __forceinline__ float warpSum(float v) {
    #pragma unroll
    for (int o = 16; o; o >>= 1) v += __shfl_xor_sync(0xFFFFFFFFu, v, o);
    return v;
}
__device__ __forceinline__ unsigned f2tf32(float x) {
    unsigned r;
    asm("cvt.rna.tf32.f32 %0, %1;" : "=r"(r) : "f"(x));
    return r;
}

#define MMA8(acc, A0,A1,A2,A3, B0,B1)                                         \
    asm volatile(                                                             \
        "mma.sync.aligned.m16n8k8.row.col.f32.tf32.tf32.f32 "                 \
        "{%0,%1,%2,%3}, {%4,%5,%6,%7}, {%8,%9}, {%0,%1,%2,%3};"               \
        : "+f"((acc)[0]), "+f"((acc)[1]), "+f"((acc)[2]), "+f"((acc)[3])      \
        : "r"(A0), "r"(A1), "r"(A2), "r"(A3), "r"(B0), "r"(B1))

// ---------------------------------------------------------------------------
// TF32 tensor-core GEMM, cp.async double-buffered, FAT WARP TILES.
// C[128,128] tile of A[M,K] @ B[N,K]^T. 128 threads = 4 warps, 64x64/warp.
// Per ks-step per warp: 32 LDS + 32 CVT feed 32 HMMA (2:1 reuse vs 3:2 before)
// -> tensor pipe becomes the binding constraint instead of the issue port.
// Dynamic smem: 2 stages x (As[128*36] + Bs[128*36]) floats = 73728 B.
// ---------------------------------------------------------------------------
#define BM 128
#define BN 128
#define BK 32
#define PIT 36
#define GEMM_SMEM (2 * (BM + BN) * PIT * 4)

__device__ __forceinline__ void cp16(float* dst, const float* src) {
    unsigned d = (unsigned)__cvta_generic_to_shared(dst);
    asm volatile("cp.async.ca.shared.global [%0], [%1], 16;" :: "r"(d), "l"(src));
}

__device__ __forceinline__ void gemm_body(
        const float* __restrict__ A, const float* __restrict__ B,
        float* __restrict__ C, int K, int ldc, int m0, int n0b, int n0c,
        float* sA, float* sB) {
    const int tid = threadIdx.x;            // 0..127
    const int wid = tid >> 5, lane = tid & 31;
    const int wm = (wid & 1) * 64;          // warp m-offset (2x2 warp grid)
    const int wn = (wid >> 1) * 64;         // warp n-offset
    const int g = lane >> 2, c = lane & 3;

    float acc[4][8][4];
    #pragma unroll
    for (int mi = 0; mi < 4; mi++)
        #pragma unroll
        for (int ni = 0; ni < 8; ni++)
            #pragma unroll
            for (int r = 0; r < 4; r++) acc[mi][ni][r] = 0.f;

    // async stage loader: 128 threads x 8 passes x (A16B + B16B)
    #define ISSUE(st, k0)                                                     \
        do {                                                                  \
            _Pragma("unroll")                                                 \
            for (int l = 0; l < 8; l++) {                                     \
                int idx = tid + l * 128;                                      \
                int row = idx >> 3;                                           \
                int c4  = (idx & 7) * 4;                                      \
                cp16(sA + (st) * BM * PIT + row * PIT + c4,                   \
                     A + (long)(m0 + row) * K + (k0) + c4);                   \
                cp16(sB + (st) * BN * PIT + row * PIT + c4,                   \
                     B + (long)(n0b + row) * K + (k0) + c4);                  \
            }                                                                 \
            asm volatile("cp.async.commit_group;");                           \
        } while (0)

    ISSUE(0, 0);
    const int NIT = K / BK;
    for (int it = 0; it < NIT; it++) {
        if (it + 1 < NIT) {
            ISSUE((it + 1) & 1, (it + 1) * BK);
            asm volatile("cp.async.wait_group 1;");
        } else {
            asm volatile("cp.async.wait_group 0;");
        }
        __syncthreads();
        const float* As = sA + (it & 1) * BM * PIT;
        const float* Bs = sB + (it & 1) * BN * PIT;

        #pragma unroll
        for (int ks = 0; ks < BK; ks += 8) {
            unsigned a[4][4], b[8][2];
            #pragma unroll
            for (int mi = 0; mi < 4; mi++) {
                int r = wm + mi * 16;
                a[mi][0] = f2tf32(As[(r + g)     * PIT + ks + c]);
                a[mi][1] = f2tf32(As[(r + 8 + g) * PIT + ks + c]);
                a[mi][2] = f2tf32(As[(r + g)     * PIT + ks + c + 4]);
                a[mi][3] = f2tf32(As[(r + 8 + g) * PIT + ks + c + 4]);
            }
            #pragma unroll
            for (int ni = 0; ni < 8; ni++) {
                b[ni][0] = f2tf32(Bs[(wn + ni * 8 + g) * PIT + ks + c]);
                b[ni][1] = f2tf32(Bs[(wn + ni * 8 + g) * PIT + ks + c + 4]);
            }
            #pragma unroll
            for (int mi = 0; mi < 4; mi++)
                #pragma unroll
                for (int ni = 0; ni < 8; ni++)
                    MMA8(acc[mi][ni], a[mi][0], a[mi][1], a[mi][2], a[mi][3],
                         b[ni][0], b[ni][1]);
        }
        __syncthreads();
    }
    #undef ISSUE

    #pragma unroll
    for (int mi = 0; mi < 4; mi++) {
        #pragma unroll
        for (int ni = 0; ni < 8; ni++) {
            int row0 = m0 + wm + mi * 16 + g;
            int col  = n0c + wn + ni * 8 + 2 * c;
            *(float2*)&C[(long)row0 * ldc + col] =
                make_float2(acc[mi][ni][0], acc[mi][ni][1]);
            *(float2*)&C[(long)(row0 + 8) * ldc + col] =
                make_float2(acc[mi][ni][2], acc[mi][ni][3]);
        }
    }
}

__global__ __launch_bounds__(128, 2) void gemm_tf32(
        const float* __restrict__ A, const float* __restrict__ B,
        float* __restrict__ C, int K, int ldc) {
    extern __shared__ float smem[];
    gemm_body(A, B, C, K, ldc, blockIdx.y * BM, blockIdx.x * BN, blockIdx.x * BN,
              smem, smem + 2 * BM * PIT);
}

__global__ __launch_bounds__(128, 2) void gemm_qkv(
        const float* __restrict__ A,
        const float* __restrict__ Wq, const float* __restrict__ Wk,
        const float* __restrict__ Wv, float* __restrict__ C) {
    extern __shared__ float smem[];
    const int nb = blockIdx.x;
    const float* Bp;
    int n0b, n0c;
    if (nb < 8)       { Bp = Wq; n0b = nb * 128;        n0c = n0b; }
    else if (nb < 10) { Bp = Wk; n0b = (nb - 8) * 128;  n0c = 1024 + n0b; }
    else              { Bp = Wv; n0b = (nb - 10) * 128; n0c = 1280 + n0b; }
    gemm_body(A, Bp, C, Cq, NQKV, blockIdx.y * BM, n0b, n0c,
              smem, smem + 2 * BM * PIT);
}

// ---------------------------------------------------------------------------
// Prep: gate + ve add, RoPE, RMS-norm, rearrange (+ transposed V).
// ---------------------------------------------------------------------------
__global__ void prep_kernel(const float* __restrict__ raw,
                            const float* __restrict__ x,
                            const float* __restrict__ ve,
                            const float* __restrict__ cosv,
                            const float* __restrict__ sinv,
                            const float* __restrict__ Wg,
                            float* __restrict__ Q,
                            float* __restrict__ Kd,
                            float* __restrict__ Vt) {
    const int r = blockIdx.x;
    const int b = r >> 10;
    const int t = r & 1023;
    const int w = threadIdx.x >> 5;
    const int lane = threadIdx.x & 31;

    const float c = cosv[t * 32 + lane];
    const float s = sinv[t * 32 + lane];
    const float* row = raw + (long)r * NQKV;
    const float EPS = 1.1920928955078125e-07f;

    #pragma unroll
    for (int hh = 0; hh < 4; hh++) {
        int h = w + hh * 4;
        float x1 = row[h * 64 + lane];
        float x2 = row[h * 64 + 32 + lane];
        float y1 = x1 * c + x2 * s;
        float y2 = -x1 * s + x2 * c;
        float ss = warpSum(y1 * y1 + y2 * y2);
        float rn = rsqrtf(ss * (1.f / 64.f) + EPS) * 1.2f;
        float* qo = Q + ((long)(b * Hq + h) * Tq + t) * 64;
        qo[lane] = y1 * rn;
        qo[lane + 32] = y2 * rn;
    }
    {
        float x1 = row[1024 + w * 64 + lane];
        float x2 = row[1024 + w * 64 + 32 + lane];
        float y1 = x1 * c + x2 * s;
        float y2 = -x1 * s + x2 * c;
        float ss = warpSum(y1 * y1 + y2 * y2);
        float rn = rsqrtf(ss * (1.f / 64.f) + EPS) * 1.2f;
        float* ko = Kd + ((long)(b * HKVq + w) * Tq + t) * 64;
        ko[lane] = y1 * rn;
        ko[lane + 32] = y2 * rn;
    }
    {
        float gv = 0.f;
        if (lane < GATE_CH) gv = x[(long)r * Cq + lane] * Wg[w * GATE_CH + lane];
        gv = warpSum(gv);
        float gate = 3.f / (1.f + __expf(-gv));
        float v1 = row[1280 + w * 64 + lane]      + gate * ve[(long)r * 256 + w * 64 + lane];
        float v2 = row[1280 + w * 64 + 32 + lane] + gate * ve[(long)r * 256 + w * 64 + 32 + lane];
        float* vb = Vt + ((long)(b * HKVq + w) * 64) * Tq;
        vb[(long)lane * Tq + t]        = v1;
        vb[(long)(lane + 32) * Tq + t] = v2;
    }
}

// ---------------------------------------------------------------------------
// Tensor-core sliding-window attention (tf32). (unchanged)
// ---------------------------------------------------------------------------
#define KWIN 320
#define KP   68
#define VTP  324
#define SM_Q   0
#define SM_K   (SM_Q + 64 * KP)
#define SM_VT  (SM_K + KWIN * KP)
#define SM_P   (SM_VT + 64 * VTP)
#define SM_ST  (SM_P + 64 * KP)
#define ATTN_WORDS (SM_ST + 256)
#define ATTN_SMEM  (ATTN_WORDS * 4)

__global__ __launch_bounds__(256) void attn_mma(
        const float* __restrict__ Q, const float* __restrict__ Kd,
        const float* __restrict__ Vt, float* __restrict__ Y,
        const int* __restrict__ wptr) {
    extern __shared__ unsigned sm[];
    unsigned* Qs  = sm + SM_Q;
    unsigned* Ks  = sm + SM_K;
    unsigned* Vts = sm + SM_VT;
    unsigned* Ps  = sm + SM_P;
    float* smax = (float*)(sm + SM_ST);
    float* ssum = smax + 128;

    const int W = *wptr;
    const int bh = blockIdx.y;
    const int b = bh >> 4;
    const int h = bh & 15;
    const int bg = (b << 2) | (h >> 2);
    const int qt0 = blockIdx.x * 64;
    const int ks0 = qt0 - 256;

    const int tid = threadIdx.x;
    const int wid = tid >> 5, lane = tid & 31;
    const int kh = wid >> 2, mt = wid & 3;
    const int g = lane >> 2, c = lane & 3;

    const float* Qb  = Q  + (long)bh * Tq * 64;
    const float* Kb  = Kd + (long)bg * Tq * 64;
    const float* Vtb = Vt + (long)bg * 64 * Tq;

    #pragma unroll
    for (int r = 0; r < 8; r++) {
        int q = wid * 8 + r;
        float2 v = *(const float2*)(Qb + (long)(qt0 + q) * 64 + lane * 2);
        Qs[q * KP + lane * 2]     = f2tf32(v.x);
        Qs[q * KP + lane * 2 + 1] = f2tf32(v.y);
    }
    #pragma unroll
    for (int r = 0; r < 40; r++) {
        int jl = wid * 40 + r;
        int jg = min(max(ks0 + jl, 0), Tq - 1);
        float2 v = *(const float2*)(Kb + (long)jg * 64 + lane * 2);
        Ks[jl * KP + lane * 2]     = f2tf32(v.x);
        Ks[jl * KP + lane * 2 + 1] = f2tf32(v.y);
    }
    #pragma unroll
    for (int r = 0; r < 8; r++) {
        int d = wid * 8 + r;
        #pragma unroll
        for (int j = 0; j < KWIN; j += 32) {
            int jg = min(max(ks0 + j + lane, 0), Tq - 1);
            Vts[d * VTP + j + lane] = f2tf32(Vtb[(long)d * Tq + jg]);
        }
    }
    __syncthreads();

    float S[20][4];
    #pragma unroll
    for (int nt = 0; nt < 20; nt++)
        #pragma unroll
        for (int r = 0; r < 4; r++) S[nt][r] = 0.f;

    const int q0 = mt * 16;
    #pragma unroll
    for (int ks = 0; ks < 8; ks++) {
        unsigned a0 = Qs[(q0 + g)     * KP + ks * 8 + c];
        unsigned a1 = Qs[(q0 + 8 + g) * KP + ks * 8 + c];
        unsigned a2 = Qs[(q0 + g)     * KP + ks * 8 + c + 4];
        unsigned a3 = Qs[(q0 + 8 + g) * KP + ks * 8 + c + 4];
        #pragma unroll
        for (int nt = 0; nt < 20; nt++) {
            int key0 = ((nt >> 2) * 2 + kh) * 32 + (nt & 3) * 8;
            unsigned b0 = Ks[(key0 + g) * KP + ks * 8 + c];
            unsigned b1 = Ks[(key0 + g) * KP + ks * 8 + c + 4];
            MMA8(S[nt], a0, a1, a2, a3, b0, b1);
        }
    }

    const int i0 = qt0 + q0 + g, i1 = i0 + 8;
    float mx0 = -1e30f, mx1 = -1e30f;
    #pragma unroll
    for (int nt = 0; nt < 20; nt++) {
        int key0 = ((nt >> 2) * 2 + kh) * 32 + (nt & 3) * 8;
        int j0 = ks0 + key0 + 2 * c, j1 = j0 + 1;
        S[nt][0] = (j0 >= 0 && j0 <= i0 && (i0 - j0) <= W) ? S[nt][0] * 0.125f : -1e30f;
        S[nt][1] = (j1 >= 0 && j1 <= i0 && (i0 - j1) <= W) ? S[nt][1] * 0.125f : -1e30f;
        S[nt][2] = (j0 >= 0 && j0 <= i1 && (i1 - j0) <= W) ? S[nt][2] * 0.125f : -1e30f;
        S[nt][3] = (j1 >= 0 && j1 <= i1 && (i1 - j1) <= W) ? S[nt][3] * 0.125f : -1e30f;
        mx0 = fmaxf(mx0, fmaxf(S[nt][0], S[nt][1]));
        mx1 = fmaxf(mx1, fmaxf(S[nt][2], S[nt][3]));
    }
    #pragma unroll
    for (int o = 1; o < 4; o <<= 1) {
        mx0 = fmaxf(mx0, __shfl_xor_sync(0xFFFFFFFFu, mx0, o));
        mx1 = fmaxf(mx1, __shfl_xor_sync(0xFFFFFFFFu, mx1, o));
    }
    if (c == 0) {
        smax[kh * 64 + q0 + g]     = mx0;
        smax[kh * 64 + q0 + g + 8] = mx1;
    }
    __syncthreads();
    const float m0 = fmaxf(smax[q0 + g],     smax[64 + q0 + g]);
    const float m1 = fmaxf(smax[q0 + g + 8], smax[64 + q0 + g + 8]);

    float s0 = 0.f, s1 = 0.f;
    #pragma unroll
    for (int nt = 0; nt < 20; nt++) {
        S[nt][0] = __expf(S[nt][0] - m0);
        S[nt][1] = __expf(S[nt][1] - m0);
        S[nt][2] = __expf(S[nt][2] - m1);
        S[nt][3] = __expf(S[nt][3] - m1);
        s0 += S[nt][0] + S[nt][1];
        s1 += S[nt][2] + S[nt][3];
    }
    #pragma unroll
    for (int o = 1; o < 4; o <<= 1) {
        s0 += __shfl_xor_sync(0xFFFFFFFFu, s0, o);
        s1 += __shfl_xor_sync(0xFFFFFFFFu, s1, o);
    }
    if (c == 0) {
        ssum[kh * 64 + q0 + g]     = s0;
        ssum[kh * 64 + q0 + g + 8] = s1;
    }

    float O[4][4];
    #pragma unroll
    for (int nd = 0; nd < 4; nd++)
        #pragma unroll
        for (int r = 0; r < 4; r++) O[nd][r] = 0.f;
    const int oh = kh;

    #pragma unroll
    for (int ck = 0; ck < 5; ck++) {
        __syncthreads();
        #pragma unroll
        for (int j = 0; j < 4; j++) {
            int nt = 4 * ck + j;
            int colb = kh * 32 + j * 8;
            Ps[(q0 + g)     * KP + colb + 2 * c]     = f2tf32(S[nt][0]);
            Ps[(q0 + g)     * KP + colb + 2 * c + 1] = f2tf32(S[nt][1]);
            Ps[(q0 + g + 8) * KP + colb + 2 * c]     = f2tf32(S[nt][2]);
            Ps[(q0 + g + 8) * KP + colb + 2 * c + 1] = f2tf32(S[nt][3]);
        }
        __syncthreads();
        #pragma unroll
        for (int ks = 0; ks < 8; ks++) {
            unsigned a0 = Ps[(q0 + g)     * KP + ks * 8 + c];
            unsigned a1 = Ps[(q0 + 8 + g) * KP + ks * 8 + c];
            unsigned a2 = Ps[(q0 + g)     * KP + ks * 8 + c + 4];
            unsigned a3 = Ps[(q0 + 8 + g) * KP + ks * 8 + c + 4];
            int kb = ck * 64 + ks * 8;
            #pragma unroll
            for (int nd = 0; nd < 4; nd++) {
                int d0 = oh * 32 + nd * 8;
                unsigned b0 = Vts[(d0 + g) * VTP + kb + c];
                unsigned b1 = Vts[(d0 + g) * VTP + kb + c + 4];
                MMA8(O[nd], a0, a1, a2, a3, b0, b1);
            }
        }
    }
    __syncthreads();

    const float inv0 = 1.f / (ssum[q0 + g]     + ssum[64 + q0 + g]);
    const float inv1 = 1.f / (ssum[q0 + g + 8] + ssum[64 + q0 + g + 8]);
    const int row0 = qt0 + q0 + g;
    #pragma unroll
    for (int nd = 0; nd < 4; nd++) {
        int col = h * 64 + oh * 32 + nd * 8 + 2 * c;
        *(float2*)&Y[((long)(b * Tq + row0) * Cq) + col] =
            make_float2(O[nd][0] * inv0, O[nd][1] * inv0);
        *(float2*)&Y[((long)(b * Tq + row0 + 8) * Cq) + col] =
            make_float2(O[nd][2] * inv1, O[nd][3] * inv1);
    }
}

// ---------------------------------------------------------------------------
extern "C" void kernel_launch(void* const* d_in, const int* in_sizes, int n_in,
                              void* d_out, int out_size) {
    const float* x    = (const float*)d_in[0];
    const float* ve   = (const float*)d_in[1];
    const float* cosv = (const float*)d_in[2];
    const float* sinv = (const float*)d_in[3];
    const float* Wq   = (const float*)d_in[4];
    const float* Wk   = (const float*)d_in[5];
    const float* Wv   = (const float*)d_in[6];
    const float* Wo   = (const float*)d_in[7];
    const float* Wg   = (const float*)d_in[8];
    const int*   wptr = (const int*)d_in[9];
    float* out = (float*)d_out;

    float *raw, *Q, *K, *Vt, *Y;
    cudaGetSymbolAddress((void**)&raw, g_raw);
    cudaGetSymbolAddress((void**)&Q, g_Q);
    cudaGetSymbolAddress((void**)&K, g_K);
    cudaGetSymbolAddress((void**)&Vt, g_Vt);
    cudaGetSymbolAddress((void**)&Y, g_Y);

    cudaFuncSetAttribute(attn_mma,
                         cudaFuncAttributeMaxDynamicSharedMemorySize, ATTN_SMEM);
    cudaFuncSetAttribute(gemm_tf32,
                         cudaFuncAttributeMaxDynamicSharedMemorySize, GEMM_SMEM);
    cudaFuncSetAttribute(gemm_qkv,
                         cudaFuncAttributeMaxDynamicSharedMemorySize, GEMM_SMEM);

    // fused QKV projection (tf32 tensor cores, fat warp tiles)
    gemm_qkv<<<dim3(12, MROWS/BM), 128, GEMM_SMEM>>>(x, Wq, Wk, Wv, raw);

    // gate/ve/rope/rmsnorm/rearrange (+V transpose)
    prep_kernel<<<MROWS, 128>>>(raw, x, ve, cosv, sinv, Wg, Q, K, Vt);

    // tensor-core sliding-window attention
    attn_mma<<<dim3(Tq/64, Bq*Hq), 256, ATTN_SMEM>>>(Q, K, Vt, Y, wptr);

    // output projection (tf32 tensor cores, fat warp tiles)
    gemm_tf32<<<dim3(Cq/BN, MROWS/BM), 128, GEMM_SMEM>>>(Y, Wo, out, Cq, Cq);
    (void)in_sizes; (void)n_in; (void)out_size;
}